// round 7
// baseline (speedup 1.0000x reference)
#include <cuda_runtime.h>
#include <math.h>

typedef unsigned long long ull;

#define FULLMASK 0xFFFFFFFFu
#define FEAT 192
#define NDIM 64
#define NPROXY 64
#define MAXN 50000
#define MAXR 512
#define PK 194          // pitch for K=192 tiles: rows offset 2 banks -> conflict-free LDS.64
#define PJ 66           // pitch for J=64 tiles
#define NT 48           // node tile for tail kernels

// ---------------- static scratch ----------------
static __device__ float g_out[MAXN * FEAT];     // concat outputs [N,192]
static __device__ float g_pf[MAXN * FEAT];      // proxy_feature scratch [N,192]
static __device__ float g_reln[MAXR * NDIM];    // normalized rel_emb rows
static __device__ float g_attrel[2 * MAXR];     // per-(layer,rel) attention scalar
static __device__ float g_pinv[NPROXY];         // 1/||proxy_row||

// ---------------- helpers ----------------
__device__ __forceinline__ ull ffma2(ull a, ull b, ull c) {
    ull d;
    asm("fma.rn.f32x2 %0, %1, %2, %3;" : "=l"(d) : "l"(a), "l"(b), "l"(c));
    return d;
}
__device__ __forceinline__ void unpack2(ull v, float& lo, float& hi) {
    asm("mov.b64 {%0, %1}, %2;" : "=f"(lo), "=f"(hi) : "l"(v));
}
__device__ __forceinline__ float warpSum(float v) {
    #pragma unroll
    for (int o = 16; o; o >>= 1) v += __shfl_xor_sync(FULLMASK, v, o);
    return v;
}
__device__ __forceinline__ float sigmoidf_(float x) { return 1.f / (1.f + __expf(-x)); }

// ---------------- prep: normalize rel rows + per-layer attention scalars ----------------
__global__ void prep_rel_kernel(const float* __restrict__ rel_emb,
                                const float* __restrict__ ak, int R, int L)
{
    __shared__ float red[2];
    int r = blockIdx.x, t = threadIdx.x;     // 64 threads
    float v = rel_emb[r * NDIM + t];
    float ss = warpSum(v * v);
    int w = t >> 5, ln = t & 31;
    if (ln == 0) red[w] = ss;
    __syncthreads();
    float inv = 1.f / fmaxf(sqrtf(red[0] + red[1]), 1e-12f);
    float vn = v * inv;
    g_reln[r * NDIM + t] = vn;
    for (int l = 0; l < L; l++) {
        __syncthreads();
        float a = warpSum(vn * ak[l * NDIM + t]);
        if (ln == 0) red[w] = a;
        __syncthreads();
        if (t == 0) g_attrel[l * R + r] = red[0] + red[1];
    }
}

// ---------------- prep: proxy row inverse norms ----------------
__global__ void prep_proxy_kernel(const float* __restrict__ proxy)
{
    __shared__ float red[6];
    int j = blockIdx.x, t = threadIdx.x;     // 192 threads
    float v = proxy[j * FEAT + t];
    float s = warpSum(v * v);
    if ((t & 31) == 0) red[t >> 5] = s;
    __syncthreads();
    if (t == 0) {
        float tot = red[0] + red[1] + red[2] + red[3] + red[4] + red[5];
        g_pinv[j] = 1.f / fmaxf(sqrtf(tot), 1e-12f);
    }
}

// ---------------- tanh(features) -> outputs[:, 0:64] ----------------
__global__ void tanh_kernel(const float* __restrict__ feat, int N)
{
    int i = blockIdx.x * blockDim.x + threadIdx.x;
    if (i < N * (NDIM / 4)) {
        float4 v = ((const float4*)feat)[i];
        int n = i >> 4, d4 = (i & 15) * 4;
        float4 o;
        o.x = tanhf(v.x); o.y = tanhf(v.y); o.z = tanhf(v.z); o.w = tanhf(v.w);
        *(float4*)(g_out + n * FEAT + d4) = o;
    }
}

// ---------------- GNN layer: 2 nodes/warp, 16 lanes x 4 dims, 4-edge ILP ----------------
__global__ __launch_bounds__(256) void layer_kernel(
    const int* __restrict__ src, const int* __restrict__ rid,
    int l, int col_in, int col_out, int N, int deg, int R)
{
    __shared__ float4 ec[16][32];     // [node slot][edge] = {h_off, r_off, w, -}
    const int tid = threadIdx.x;
    const int warp = tid >> 5, lane = tid & 31;
    const int half = lane >> 4, hl = lane & 15;
    int node = blockIdx.x * 16 + warp * 2 + half;
    if (node >= N) node = N - 1;      // duplicate work, identical writes (safe)
    const int slot = warp * 2 + half;
    const float* __restrict__ attrel = g_attrel + l * R;
    const int e0 = node * deg;

    // softmax over deg edges using 16 lanes (<=2 edges per lane)
    int ea = hl, eb = hl + 16;
    bool va = ea < deg, vb = eb < deg;
    int sa = 0, ra = 0, sb = 0, rb = 0;
    float aa = -3.0e38f, ab = -3.0e38f;
    if (va) { sa = src[e0 + ea]; ra = rid[e0 + ea]; aa = attrel[ra]; }
    if (vb) { sb = src[e0 + eb]; rb = rid[e0 + eb]; ab = attrel[rb]; }
    float m = fmaxf(aa, ab);
    #pragma unroll
    for (int o = 8; o; o >>= 1) m = fmaxf(m, __shfl_xor_sync(FULLMASK, m, o));
    float xa = va ? __expf(aa - m) : 0.f;
    float xb = vb ? __expf(ab - m) : 0.f;
    float s = xa + xb;
    #pragma unroll
    for (int o = 8; o; o >>= 1) s += __shfl_xor_sync(FULLMASK, s, o);
    float is = 1.f / s;
    if (va) ec[slot][ea] = make_float4(__int_as_float(sa * FEAT + col_in),
                                       __int_as_float(ra * NDIM), xa * is, 0.f);
    if (vb) ec[slot][eb] = make_float4(__int_as_float(sb * FEAT + col_in),
                                       __int_as_float(rb * NDIM), xb * is, 0.f);
    __syncwarp();

    const int d4 = hl * 4;
    float4 acc = make_float4(0.f, 0.f, 0.f, 0.f);
    int e = 0;
    for (; e + 4 <= deg; e += 4) {
        float4 t0 = ec[slot][e + 0], t1 = ec[slot][e + 1];
        float4 t2 = ec[slot][e + 2], t3 = ec[slot][e + 3];
        const float4 h0 = *(const float4*)(g_out  + __float_as_int(t0.x) + d4);
        const float4 r0 = *(const float4*)(g_reln + __float_as_int(t0.y) + d4);
        const float4 h1 = *(const float4*)(g_out  + __float_as_int(t1.x) + d4);
        const float4 r1 = *(const float4*)(g_reln + __float_as_int(t1.y) + d4);
        const float4 h2 = *(const float4*)(g_out  + __float_as_int(t2.x) + d4);
        const float4 r2 = *(const float4*)(g_reln + __float_as_int(t2.y) + d4);
        const float4 h3 = *(const float4*)(g_out  + __float_as_int(t3.x) + d4);
        const float4 r3 = *(const float4*)(g_reln + __float_as_int(t3.y) + d4);
        float dp0 = fmaf(h0.x, r0.x, fmaf(h0.y, r0.y, fmaf(h0.z, r0.z, h0.w * r0.w)));
        float dp1 = fmaf(h1.x, r1.x, fmaf(h1.y, r1.y, fmaf(h1.z, r1.z, h1.w * r1.w)));
        float dp2 = fmaf(h2.x, r2.x, fmaf(h2.y, r2.y, fmaf(h2.z, r2.z, h2.w * r2.w)));
        float dp3 = fmaf(h3.x, r3.x, fmaf(h3.y, r3.y, fmaf(h3.z, r3.z, h3.w * r3.w)));
        #pragma unroll
        for (int o = 8; o; o >>= 1) {          // 4 independent shfl trees
            dp0 += __shfl_xor_sync(FULLMASK, dp0, o);
            dp1 += __shfl_xor_sync(FULLMASK, dp1, o);
            dp2 += __shfl_xor_sync(FULLMASK, dp2, o);
            dp3 += __shfl_xor_sync(FULLMASK, dp3, o);
        }
        float c0 = -2.f * dp0, c1 = -2.f * dp1, c2 = -2.f * dp2, c3 = -2.f * dp3;
        acc.x = fmaf(t0.z, fmaf(c0, r0.x, h0.x), acc.x);
        acc.y = fmaf(t0.z, fmaf(c0, r0.y, h0.y), acc.y);
        acc.z = fmaf(t0.z, fmaf(c0, r0.z, h0.z), acc.z);
        acc.w = fmaf(t0.z, fmaf(c0, r0.w, h0.w), acc.w);
        acc.x = fmaf(t1.z, fmaf(c1, r1.x, h1.x), acc.x);
        acc.y = fmaf(t1.z, fmaf(c1, r1.y, h1.y), acc.y);
        acc.z = fmaf(t1.z, fmaf(c1, r1.z, h1.z), acc.z);
        acc.w = fmaf(t1.z, fmaf(c1, r1.w, h1.w), acc.w);
        acc.x = fmaf(t2.z, fmaf(c2, r2.x, h2.x), acc.x);
        acc.y = fmaf(t2.z, fmaf(c2, r2.y, h2.y), acc.y);
        acc.z = fmaf(t2.z, fmaf(c2, r2.z, h2.z), acc.z);
        acc.w = fmaf(t2.z, fmaf(c2, r2.w, h2.w), acc.w);
        acc.x = fmaf(t3.z, fmaf(c3, r3.x, h3.x), acc.x);
        acc.y = fmaf(t3.z, fmaf(c3, r3.y, h3.y), acc.y);
        acc.z = fmaf(t3.z, fmaf(c3, r3.z, h3.z), acc.z);
        acc.w = fmaf(t3.z, fmaf(c3, r3.w, h3.w), acc.w);
    }
    for (; e < deg; e++) {
        float4 t = ec[slot][e];
        const float4 h = *(const float4*)(g_out  + __float_as_int(t.x) + d4);
        const float4 r = *(const float4*)(g_reln + __float_as_int(t.y) + d4);
        float dp = fmaf(h.x, r.x, fmaf(h.y, r.y, fmaf(h.z, r.z, h.w * r.w)));
        #pragma unroll
        for (int o = 8; o; o >>= 1) dp += __shfl_xor_sync(FULLMASK, dp, o);
        float c = -2.f * dp;
        acc.x = fmaf(t.z, fmaf(c, r.x, h.x), acc.x);
        acc.y = fmaf(t.z, fmaf(c, r.y, h.y), acc.y);
        acc.z = fmaf(t.z, fmaf(c, r.z, h.z), acc.z);
        acc.w = fmaf(t.z, fmaf(c, r.w, h.w), acc.w);
    }
    float4 o4;
    o4.x = tanhf(acc.x); o4.y = tanhf(acc.y);
    o4.z = tanhf(acc.z); o4.w = tanhf(acc.w);
    *(float4*)(g_out + node * FEAT + col_out + d4) = o4;
}

// ---------------- proxy kernel: logits + softmax + proxy_feature -> g_pf ----------------
// smem floats: o_s 48*PK | att 48*PJ | pT 48*PJ | inv 48   (~63 KB -> 3 CTAs/SM)
#define PA_OS   0
#define PA_ATT  (NT * PK)
#define PA_PT   (NT * PK + NT * PJ)
#define PA_INV  (NT * PK + 2 * NT * PJ)
#define PA_FLOATS (PA_INV + NT)
#define PA_BYTES  (PA_FLOATS * 4)

__global__ __launch_bounds__(256, 3) void proxy_kernel(
    const float* __restrict__ proxy, int N)
{
    extern __shared__ float sm[];
    float* o_s   = sm + PA_OS;
    float* att_s = sm + PA_ATT;
    float* pT_s  = sm + PA_PT;
    float* inv_s = sm + PA_INV;
    const int tid = threadIdx.x;
    const int n0 = blockIdx.x * NT;

    // load o tile (k-major, pitch PK)
    for (int idx = tid; idx < NT * 96; idx += 256) {
        int n = idx / 96, k2 = idx - n * 96;
        float2 v = make_float2(0.f, 0.f);
        if (n0 + n < N) v = *(const float2*)(g_out + (n0 + n) * FEAT + 2 * k2);
        *(float2*)(o_s + n * PK + 2 * k2) = v;
    }
    __syncthreads();

    // per-node inverse norms (192 threads: 4 per node)
    if (tid < NT * 4) {
        int n = tid >> 2, sub = tid & 3;
        float ss = 0.f;
        for (int d = sub; d < FEAT; d += 4) { float v = o_s[n * PK + d]; ss = fmaf(v, v, ss); }
        ss += __shfl_xor_sync(FULLMASK, ss, 1);
        ss += __shfl_xor_sync(FULLMASK, ss, 2);
        if (sub == 0) inv_s[n] = 1.f / fmaxf(sqrtf(ss), 1e-12f);
    }
    __syncthreads();

    const int nq = tid & 15;
    const int rest = tid >> 4;       // 0..15

    // P1: logits. A = o_s rows (smem, 16 distinct), B = proxy rows (__ldg broadcast)
    {
        const float* bg = proxy + (rest * 4) * FEAT;
        ull acc[3][4];
        #pragma unroll
        for (int i = 0; i < 3; i++)
            #pragma unroll
            for (int j = 0; j < 4; j++) acc[i][j] = 0ull;
        #pragma unroll 2
        for (int k = 0; k < FEAT; k += 2) {
            ull A[3], B[4];
            #pragma unroll
            for (int i = 0; i < 3; i++) A[i] = *(const ull*)(o_s + (nq + 16 * i) * PK + k);
            #pragma unroll
            for (int j = 0; j < 4; j++) B[j] = __ldg((const ull*)(bg + j * FEAT + k));
            #pragma unroll
            for (int i = 0; i < 3; i++)
                #pragma unroll
                for (int j = 0; j < 4; j++) acc[i][j] = ffma2(A[i], B[j], acc[i][j]);
        }
        float pv[4];
        #pragma unroll
        for (int j = 0; j < 4; j++) pv[j] = g_pinv[rest * 4 + j];
        #pragma unroll
        for (int i = 0; i < 3; i++) {
            int n = nq + 16 * i;
            float in_ = inv_s[n];
            #pragma unroll
            for (int j = 0; j < 4; j++) {
                float lo, hi; unpack2(acc[i][j], lo, hi);
                att_s[n * PJ + rest * 4 + j] = (lo + hi) * in_ * pv[j];
            }
        }
    }
    __syncthreads();

    // softmax over 64 proxies per node (4 threads per node)
    if (tid < NT * 4) {
        int n = tid >> 2, sub = tid & 3;
        float vbuf[16];
        float m = -3.0e38f;
        #pragma unroll
        for (int t = 0; t < 16; t++) { vbuf[t] = att_s[n * PJ + sub + 4 * t]; m = fmaxf(m, vbuf[t]); }
        m = fmaxf(m, __shfl_xor_sync(FULLMASK, m, 1));
        m = fmaxf(m, __shfl_xor_sync(FULLMASK, m, 2));
        float s = 0.f;
        #pragma unroll
        for (int t = 0; t < 16; t++) { vbuf[t] = __expf(vbuf[t] - m); s += vbuf[t]; }
        s += __shfl_xor_sync(FULLMASK, s, 1);
        s += __shfl_xor_sync(FULLMASK, s, 2);
        float is = 1.f / s;
        #pragma unroll
        for (int t = 0; t < 16; t++) att_s[n * PJ + sub + 4 * t] = vbuf[t] * is;
    }
    __syncthreads();

    // P2: pf = o - att @ proxy, 4 d-chunks of 48 via pT slices
    for (int c = 0; c < 4; c++) {
        if (c) __syncthreads();          // prev chunk's pT reads done
        for (int idx = tid; idx < NPROXY * 48; idx += 256) {
            int j = idx / 48, dl = idx - j * 48;
            pT_s[dl * PJ + j] = __ldg(proxy + j * FEAT + c * 48 + dl);
        }
        __syncthreads();

        ull acc[3][3];
        #pragma unroll
        for (int i = 0; i < 3; i++)
            #pragma unroll
            for (int mm = 0; mm < 3; mm++) acc[i][mm] = 0ull;
        #pragma unroll 2
        for (int jp = 0; jp < NPROXY; jp += 2) {
            ull A[3], B[3];
            #pragma unroll
            for (int i = 0; i < 3; i++) A[i] = *(const ull*)(att_s + (nq + 16 * i) * PJ + jp);
            #pragma unroll
            for (int mm = 0; mm < 3; mm++) B[mm] = *(const ull*)(pT_s + (rest * 3 + mm) * PJ + jp);
            #pragma unroll
            for (int i = 0; i < 3; i++)
                #pragma unroll
                for (int mm = 0; mm < 3; mm++) acc[i][mm] = ffma2(A[i], B[mm], acc[i][mm]);
        }
        #pragma unroll
        for (int i = 0; i < 3; i++) {
            int n = nq + 16 * i;
            bool ok = (n0 + n < N);
            #pragma unroll
            for (int mm = 0; mm < 3; mm++) {
                int d = c * 48 + rest * 3 + mm;
                float lo, hi; unpack2(acc[i][mm], lo, hi);
                float pf = o_s[n * PK + d] - (lo + hi);
                if (ok) g_pf[(n0 + n) * FEAT + d] = pf;
            }
        }
    }
}

// ---------------- gate kernel: sigmoid(pf @ W^T + b) blend ----------------
__global__ __launch_bounds__(256, 3) void gate_kernel(
    const float* __restrict__ gate_w, const float* __restrict__ gate_b,
    float* __restrict__ out, int N)
{
    __shared__ float pf_s[NT * PK];      // 37.2 KB static
    const int tid = threadIdx.x;
    const int n0 = blockIdx.x * NT;

    for (int idx = tid; idx < NT * 96; idx += 256) {
        int n = idx / 96, k2 = idx - n * 96;
        float2 v = make_float2(0.f, 0.f);
        if (n0 + n < N) v = *(const float2*)(g_pf + (n0 + n) * FEAT + 2 * k2);
        *(float2*)(pf_s + n * PK + 2 * k2) = v;
    }
    __syncthreads();

    const int nq = tid & 15;
    const int rest = tid >> 4;

    for (int c = 0; c < 3; c++) {
        const float* bg = gate_w + (c * 64 + rest * 4) * FEAT;
        ull acc[3][4];
        #pragma unroll
        for (int i = 0; i < 3; i++)
            #pragma unroll
            for (int j = 0; j < 4; j++) acc[i][j] = 0ull;
        #pragma unroll 2
        for (int k = 0; k < FEAT; k += 2) {
            ull A[3], B[4];
            #pragma unroll
            for (int i = 0; i < 3; i++) A[i] = *(const ull*)(pf_s + (nq + 16 * i) * PK + k);
            #pragma unroll
            for (int j = 0; j < 4; j++) B[j] = __ldg((const ull*)(bg + j * FEAT + k));
            #pragma unroll
            for (int i = 0; i < 3; i++)
                #pragma unroll
                for (int j = 0; j < 4; j++) acc[i][j] = ffma2(A[i], B[j], acc[i][j]);
        }
        float bb[4];
        #pragma unroll
        for (int j = 0; j < 4; j++) bb[j] = __ldg(gate_b + c * 64 + rest * 4 + j);
        #pragma unroll
        for (int i = 0; i < 3; i++) {
            int n = nq + 16 * i;
            bool ok = (n0 + n < N);
            if (!ok) continue;
            #pragma unroll
            for (int j = 0; j < 4; j++) {
                int d = c * 64 + rest * 4 + j;
                float lo, hi; unpack2(acc[i][j], lo, hi);
                float g = sigmoidf_(lo + hi + bb[j]);
                float pf = pf_s[n * PK + d];
                float o = __ldg(g_out + (n0 + n) * FEAT + d);
                out[(n0 + n) * FEAT + d] = pf + g * (o - pf);
            }
        }
    }
}

// ---------------- launch ----------------
extern "C" void kernel_launch(void* const* d_in, const int* in_sizes, int n_in,
                              void* d_out, int out_size)
{
    const float* features = (const float*)d_in[0];
    const float* rel_emb  = (const float*)d_in[1];
    const float* proxy    = (const float*)d_in[2];
    const float* gate_w   = (const float*)d_in[3];
    const float* gate_b   = (const float*)d_in[4];
    const float* attn_k   = (const float*)d_in[5];
    const int*   adj      = (const int*)d_in[6];
    const int*   r_index  = (const int*)d_in[7];
    float*       out      = (float*)d_out;

    int N = in_sizes[0] / NDIM;
    int R = in_sizes[1] / NDIM;
    int E = in_sizes[6] / 2;
    int deg = E / N;
    int L = in_sizes[5] / NDIM;

    const int* src = adj + E;         // adj row 1: neighbor (col) ids
    const int* rid = r_index + E;     // r_index row 1: relation ids

    cudaFuncSetAttribute(proxy_kernel,
                         cudaFuncAttributeMaxDynamicSharedMemorySize, PA_BYTES);

    prep_rel_kernel<<<R, NDIM>>>(rel_emb, attn_k, R, L);
    prep_proxy_kernel<<<NPROXY, FEAT>>>(proxy);
    tanh_kernel<<<(N * (NDIM / 4) + 255) / 256, 256>>>(features, N);

    int lblocks = (N + 15) / 16;
    layer_kernel<<<lblocks, 256>>>(src, rid, 0, 0,    NDIM,     N, deg, R);
    layer_kernel<<<lblocks, 256>>>(src, rid, 1, NDIM, 2 * NDIM, N, deg, R);

    int tblocks = (N + NT - 1) / NT;
    proxy_kernel<<<tblocks, 256, PA_BYTES>>>(proxy, N);
    gate_kernel<<<tblocks, 256>>>(gate_w, gate_b, out, N);
}